// round 2
// baseline (speedup 1.0000x reference)
#include <cuda_runtime.h>
#include <cuda_fp16.h>
#include <cstdint>

// ============================================================================
// INT4Linear: out[M,N] = x[M,K] @ W[N,K]^T + bias
//   Harness dtypes (promoted): x fp32, weight int32 (one signed byte each,
//   two nibbles), scale fp32, bias fp32, out fp32.
//   M = 8192, N = 4096, K = 4096 (derived from in_sizes)
// Plan:
//   k1: dequant int4 -> fp16 g_W [N,K]
//   k2: convert x fp32 -> fp16 g_X [M,K]   (lossless: x values are fp16 exact)
//   k3: fp16 tensor-core GEMM (mma.sync m16n8k16, fp32 accum), 128x128x32,
//       cp.async double buffer, epilogue rounds through fp16 (+fp16 bias)
//       to mimic the reference rounding, stores fp32.
// ============================================================================

#define BM 128
#define BN 128
#define BK 32
#define LDS (BK + 8)   // smem row stride in halves (80B: 16B-aligned)

__device__ __half g_W[4096u * 4096u];   // 32 MB
__device__ __half g_X[8192u * 4096u];   // 64 MB

// ---------------------------------------------------------------------------
__device__ __forceinline__ uint32_t smem_u32(const void* p) {
    return (uint32_t)__cvta_generic_to_shared(p);
}
__device__ __forceinline__ void cp_async16(void* smem_dst, const void* gmem_src) {
    asm volatile("cp.async.cg.shared.global [%0], [%1], 16;\n"
                 :: "r"(smem_u32(smem_dst)), "l"(gmem_src));
}
__device__ __forceinline__ void cp_commit() {
    asm volatile("cp.async.commit_group;\n");
}
template <int N>
__device__ __forceinline__ void cp_wait() {
    asm volatile("cp.async.wait_group %0;\n" :: "n"(N));
}
__device__ __forceinline__ void ldmatrix_x4(uint32_t& r0, uint32_t& r1,
                                            uint32_t& r2, uint32_t& r3,
                                            const void* p) {
    asm volatile("ldmatrix.sync.aligned.m8n8.x4.shared.b16 {%0,%1,%2,%3}, [%4];\n"
                 : "=r"(r0), "=r"(r1), "=r"(r2), "=r"(r3)
                 : "r"(smem_u32(p)));
}
__device__ __forceinline__ void mma16816(float c[4],
                                         uint32_t a0, uint32_t a1, uint32_t a2, uint32_t a3,
                                         uint32_t b0, uint32_t b1) {
    asm volatile("mma.sync.aligned.m16n8k16.row.col.f32.f16.f16.f32 "
                 "{%0,%1,%2,%3}, {%4,%5,%6,%7}, {%8,%9}, {%0,%1,%2,%3};\n"
                 : "+f"(c[0]), "+f"(c[1]), "+f"(c[2]), "+f"(c[3])
                 : "r"(a0), "r"(a1), "r"(a2), "r"(a3), "r"(b0), "r"(b1));
}

// ---------------------------------------------------------------------------
// k1: dequant. packed[i] is an int32 holding one signed byte (two nibbles).
//     k even = high nibble (arithmetic >>4), k odd = low nibble (sign-fixed).
//     Each thread: 4 bytes (int4 vector load) -> 8 halves (uint4 store).
// ---------------------------------------------------------------------------
__global__ void dequant_kernel(const int* __restrict__ packed,
                               const float* __restrict__ scale_p,
                               int total_bytes) {
    int t = blockIdx.x * blockDim.x + threadIdx.x;
    int base = t * 4;
    if (base >= total_bytes) return;
    const float s = __ldg(scale_p);          // exact fp16 value promoted to fp32
    const int4 v = reinterpret_cast<const int4*>(packed)[t];
    __half out[8];
    const int b[4] = {v.x, v.y, v.z, v.w};
#pragma unroll
    for (int j = 0; j < 4; ++j) {
        int hi = b[j] >> 4;                  // arithmetic shift: signed high nibble
        int lo = ((b[j] & 15) ^ 8) - 8;      // signed low nibble
        out[2 * j]     = __float2half_rn((float)hi * s);   // exact product, RN to fp16
        out[2 * j + 1] = __float2half_rn((float)lo * s);
    }
    reinterpret_cast<uint4*>(g_W + (size_t)base * 2)[0] =
        *reinterpret_cast<const uint4*>(out);
}

// ---------------------------------------------------------------------------
// k2: x fp32 -> fp16 (lossless). 8 elements/thread.
// ---------------------------------------------------------------------------
__global__ void convert_x_kernel(const float* __restrict__ x, int total) {
    int t = blockIdx.x * blockDim.x + threadIdx.x;
    int base = t * 8;
    if (base >= total) return;
    float4 a = reinterpret_cast<const float4*>(x)[t * 2];
    float4 c = reinterpret_cast<const float4*>(x)[t * 2 + 1];
    __half out[8];
    out[0] = __float2half_rn(a.x); out[1] = __float2half_rn(a.y);
    out[2] = __float2half_rn(a.z); out[3] = __float2half_rn(a.w);
    out[4] = __float2half_rn(c.x); out[5] = __float2half_rn(c.y);
    out[6] = __float2half_rn(c.z); out[7] = __float2half_rn(c.w);
    reinterpret_cast<uint4*>(g_X + base)[0] = *reinterpret_cast<const uint4*>(out);
}

// ---------------------------------------------------------------------------
// k3: GEMM  Out[M,N] = g_X[M,K] * g_W[N,K]^T + bias[N]
//     block 128x128x32, 8 warps (2m x 4n), warp tile 64x32, fp32 accum.
// ---------------------------------------------------------------------------
__global__ __launch_bounds__(256)
void gemm_kernel(const float* __restrict__ bias,
                 float* __restrict__ Out,
                 int M, int N, int K) {
    __shared__ __half As[2][BM][LDS];
    __shared__ __half Bs[2][BN][LDS];

    const int tid  = threadIdx.x;
    const int warp = tid >> 5;
    const int lane = tid & 31;
    const int wm   = warp >> 2;   // 0..1 -> 64-row slab
    const int wn   = warp & 3;    // 0..3 -> 32-col slab
    const int bm   = blockIdx.y * BM;
    const int bn   = blockIdx.x * BN;

    float acc[4][4][4];
#pragma unroll
    for (int mf = 0; mf < 4; ++mf)
#pragma unroll
        for (int nf = 0; nf < 4; ++nf)
#pragma unroll
            for (int e = 0; e < 4; ++e) acc[mf][nf][e] = 0.0f;

    auto load_tile = [&](int buf, int k0) {
#pragma unroll
        for (int r = 0; r < 2; ++r) {
            int id  = tid + r * 256;
            int row = id >> 2;
            int c8  = (id & 3) * 8;
            cp_async16(&As[buf][row][c8], g_X + (size_t)(bm + row) * K + k0 + c8);
            cp_async16(&Bs[buf][row][c8], g_W + (size_t)(bn + row) * K + k0 + c8);
        }
    };

    const int nt = K / BK;
    load_tile(0, 0);
    cp_commit();
    cp_wait<0>();
    __syncthreads();

    for (int kt = 0; kt < nt; ++kt) {
        const int buf = kt & 1;
        if (kt + 1 < nt) { load_tile(buf ^ 1, (kt + 1) * BK); cp_commit(); }

#pragma unroll
        for (int ks = 0; ks < 2; ++ks) {
            const int k16 = ks * 16;
            uint32_t a[4][4];
#pragma unroll
            for (int mf = 0; mf < 4; ++mf) {
                ldmatrix_x4(a[mf][0], a[mf][1], a[mf][2], a[mf][3],
                            &As[buf][wm * 64 + mf * 16 + (lane & 15)][k16 + (lane >> 4) * 8]);
            }
            uint32_t b[4][2];
#pragma unroll
            for (int np = 0; np < 2; ++np) {
                uint32_t r0, r1, r2, r3;
                ldmatrix_x4(r0, r1, r2, r3,
                            &Bs[buf][wn * 32 + np * 16 + (lane & 15)][k16 + (lane >> 4) * 8]);
                b[np * 2][0]     = r0;  // n 0-7,  k 0-7
                b[np * 2][1]     = r2;  // n 0-7,  k 8-15
                b[np * 2 + 1][0] = r1;  // n 8-15, k 0-7
                b[np * 2 + 1][1] = r3;  // n 8-15, k 8-15
            }
#pragma unroll
            for (int mf = 0; mf < 4; ++mf)
#pragma unroll
                for (int nf = 0; nf < 4; ++nf)
                    mma16816(acc[mf][nf],
                             a[mf][0], a[mf][1], a[mf][2], a[mf][3],
                             b[nf][0], b[nf][1]);
        }

        if (kt + 1 < nt) cp_wait<0>();
        __syncthreads();
    }

    // epilogue: round acc -> fp16, add fp16 bias, store fp32
    //           (replicates reference's fp16 rounding chain)
#pragma unroll
    for (int mf = 0; mf < 4; ++mf) {
        const int row0 = bm + wm * 64 + mf * 16 + (lane >> 2);
#pragma unroll
        for (int nf = 0; nf < 4; ++nf) {
            const int col = bn + wn * 32 + nf * 8 + (lane & 3) * 2;
            const float2 bf = *reinterpret_cast<const float2*>(bias + col);
            const __half2 bb = __floats2half2_rn(bf.x, bf.y);
            __half2 v0 = __hadd2(__floats2half2_rn(acc[mf][nf][0], acc[mf][nf][1]), bb);
            __half2 v1 = __hadd2(__floats2half2_rn(acc[mf][nf][2], acc[mf][nf][3]), bb);
            float2 o0 = __half22float2(v0);
            float2 o1 = __half22float2(v1);
            *reinterpret_cast<float2*>(Out + (size_t)row0 * N + col)       = o0;
            *reinterpret_cast<float2*>(Out + (size_t)(row0 + 8) * N + col) = o1;
        }
    }
}

// ---------------------------------------------------------------------------
extern "C" void kernel_launch(void* const* d_in, const int* in_sizes, int n_in,
                              void* d_out, int out_size) {
    const float* x     = (const float*)d_in[0];
    const int*   wq    = (const int*)d_in[1];     // one signed byte per int32
    const float* scale = (const float*)d_in[2];
    const float* bias  = (const float*)d_in[3];
    float*       out   = (float*)d_out;

    const int O = in_sizes[3];                    // 4096
    const int K = (in_sizes[1] / O) * 2;          // 4096
    const int M = in_sizes[0] / K;                // 8192
    const int N = O;

    // 1) dequant int4 -> g_W fp16
    const int nbytes = in_sizes[1];               // byte-values count
    dequant_kernel<<<(nbytes / 4 + 255) / 256, 256>>>(wq, scale, nbytes);

    // 2) x fp32 -> g_X fp16
    const int nx = in_sizes[0];
    convert_x_kernel<<<(nx / 8 + 255) / 256, 256>>>(x, nx);

    // 3) GEMM + bias
    dim3 grid(N / BN, M / BM);
    gemm_kernel<<<grid, 256>>>(bias, out, M, N, K);
}

// round 4
// speedup vs baseline: 4.2428x; 4.2428x over previous
#include <cuda_runtime.h>
#include <cuda_fp16.h>
#include <cstdint>

// ============================================================================
// INT4Linear on GB300.
//   out[M,N] = x[M,K] @ W[N,K]^T + bias     M=8192 N=4096 K=4096
// k1: dequant int4 -> g_W fp16, PRE-SWIZZLED (SW128) blocks [N/256][K/64][2][128x64]
// k2: x fp32 -> g_X fp16, PRE-SWIZZLED blocks [M/128][K/64][128x64]
// k3: GEMM, CTA tile 128x256:
//     - sm_103a cubin: tcgen05 pipeline (cp.async.bulk + mbarrier, TMEM accum)
//     - other targets: mma.sync fallback (same global layout) so the
//       compute_103 ptxas pass compiles; driver picks the 103a cubin at run.
// ============================================================================

#if defined(__CUDA_ARCH_FEAT_SM103_ALL) || defined(__CUDA_ARCH_FEAT_SM100_ALL)
#define TC_PATH 1
#else
#define TC_PATH 0
#endif

#define KC_ELEMS 64            // K elements per chunk (fp16) -> 128B rows
#define BLK_BYTES 16384        // one 128x64 fp16 tile block
#define STAGES 4
#define STAGE_BYTES (3 * BLK_BYTES)   // A 16KB + B 32KB
#define SMEM_STAGE0 1024
#define SMEM_TOTAL_GEMM (SMEM_STAGE0 + STAGES * STAGE_BYTES)   // 197632

__device__ __half g_W[4096u * 4096u];   // 32 MB, tiled+swizzled
__device__ __half g_X[8192u * 4096u];   // 64 MB, tiled+swizzled

__host__ __device__ __forceinline__ uint32_t swz128(uint32_t o) {
    return o ^ ((o >> 3) & 0x70);
}

// ---------------------------------------------------------------------------
// common helpers
// ---------------------------------------------------------------------------
__device__ __forceinline__ uint32_t smem_u32(const void* p) {
    return (uint32_t)__cvta_generic_to_shared(p);
}
__device__ __forceinline__ void cp_async16(void* smem_dst, const void* gmem_src) {
    asm volatile("cp.async.cg.shared.global [%0], [%1], 16;\n"
                 :: "r"(smem_u32(smem_dst)), "l"(gmem_src));
}
__device__ __forceinline__ void cp_commit() {
    asm volatile("cp.async.commit_group;\n");
}
template <int N>
__device__ __forceinline__ void cp_wait() {
    asm volatile("cp.async.wait_group %0;\n" :: "n"(N));
}
__device__ __forceinline__ void ldmatrix_x4(uint32_t& r0, uint32_t& r1,
                                            uint32_t& r2, uint32_t& r3,
                                            const void* p) {
    asm volatile("ldmatrix.sync.aligned.m8n8.x4.shared.b16 {%0,%1,%2,%3}, [%4];\n"
                 : "=r"(r0), "=r"(r1), "=r"(r2), "=r"(r3)
                 : "r"(smem_u32(p)));
}
__device__ __forceinline__ void mma16816(float c[4],
                                         uint32_t a0, uint32_t a1, uint32_t a2, uint32_t a3,
                                         uint32_t b0, uint32_t b1) {
    asm volatile("mma.sync.aligned.m16n8k16.row.col.f32.f16.f16.f32 "
                 "{%0,%1,%2,%3}, {%4,%5,%6,%7}, {%8,%9}, {%0,%1,%2,%3};\n"
                 : "+f"(c[0]), "+f"(c[1]), "+f"(c[2]), "+f"(c[3])
                 : "r"(a0), "r"(a1), "r"(a2), "r"(a3), "r"(b0), "r"(b1));
}

// ---------------------------------------------------------------------------
// sm_103a-only helpers (guarded so compute_103 pass never sees tcgen05 PTX)
// ---------------------------------------------------------------------------
#if TC_PATH
__device__ __forceinline__ void mbar_init(uint32_t a, uint32_t cnt) {
    asm volatile("mbarrier.init.shared.b64 [%0], %1;" :: "r"(a), "r"(cnt) : "memory");
}
__device__ __forceinline__ void mbar_expect_tx(uint32_t a, uint32_t bytes) {
    asm volatile("mbarrier.arrive.expect_tx.shared.b64 _, [%0], %1;"
                 :: "r"(a), "r"(bytes) : "memory");
}
__device__ __forceinline__ void mbar_wait(uint32_t a, uint32_t parity) {
    uint32_t done;
    asm volatile(
        "{\n\t.reg .pred p;\n\t"
        "mbarrier.try_wait.parity.acquire.cta.shared::cta.b64 p, [%1], %2;\n\t"
        "selp.b32 %0, 1, 0, p;\n\t}"
        : "=r"(done) : "r"(a), "r"(parity) : "memory");
    if (!done) {
        asm volatile(
            "{\n\t.reg .pred P1;\n\t"
            "W0_%=:\n\t"
            "mbarrier.try_wait.parity.acquire.cta.shared::cta.b64 P1, [%0], %1, 0x989680;\n\t"
            "@P1 bra.uni W1_%=;\n\t"
            "bra.uni W0_%=;\n\t"
            "W1_%=:\n\t}"
            :: "r"(a), "r"(parity) : "memory");
    }
}
__device__ __forceinline__ void bulk_g2s(uint32_t dst, const void* src,
                                         uint32_t bytes, uint32_t mbar) {
    asm volatile(
        "cp.async.bulk.shared::cluster.global.mbarrier::complete_tx::bytes "
        "[%0], [%1], %2, [%3];"
        :: "r"(dst), "l"(src), "r"(bytes), "r"(mbar) : "memory");
}
__device__ __forceinline__ void tmem_alloc(uint32_t smem_slot, uint32_t ncols) {
    asm volatile("tcgen05.alloc.cta_group::1.sync.aligned.shared::cta.b32 [%0], %1;"
                 :: "r"(smem_slot), "r"(ncols) : "memory");
}
__device__ __forceinline__ void tmem_relinquish() {
    asm volatile("tcgen05.relinquish_alloc_permit.cta_group::1.sync.aligned;");
}
__device__ __forceinline__ void tmem_dealloc(uint32_t base, uint32_t ncols) {
    asm volatile("tcgen05.dealloc.cta_group::1.sync.aligned.b32 %0, %1;"
                 :: "r"(base), "r"(ncols));
}
__device__ __forceinline__ void mma_f16_ss(uint32_t d_tmem, uint64_t a_desc,
                                           uint64_t b_desc, uint32_t idesc,
                                           uint32_t enable) {
    asm volatile(
        "{\n\t.reg .pred p;\n\t"
        "setp.ne.u32 p, %5, 0;\n\t"
        "tcgen05.mma.cta_group::1.kind::f16 [%0], %1, %2, %3, {%4, %4, %4, %4}, p;\n\t}"
        :: "r"(d_tmem), "l"(a_desc), "l"(b_desc), "r"(idesc), "r"(0u), "r"(enable)
        : "memory");
}
__device__ __forceinline__ void tc_commit(uint32_t mbar) {
    asm volatile(
        "tcgen05.commit.cta_group::1.mbarrier::arrive::one.shared::cluster.b64 [%0];"
        :: "r"(mbar) : "memory");
}
__device__ __forceinline__ void tc_fence_after() {
    asm volatile("tcgen05.fence::after_thread_sync;" ::: "memory");
}
__device__ __forceinline__ void ldtm_x32(uint32_t* r, uint32_t addr) {
    asm volatile(
        "tcgen05.ld.sync.aligned.32x32b.x32.b32 "
        "{%0,%1,%2,%3,%4,%5,%6,%7,%8,%9,%10,%11,%12,%13,%14,%15,"
        "%16,%17,%18,%19,%20,%21,%22,%23,%24,%25,%26,%27,%28,%29,%30,%31}, [%32];"
        : "=r"(r[0]), "=r"(r[1]), "=r"(r[2]), "=r"(r[3]),
          "=r"(r[4]), "=r"(r[5]), "=r"(r[6]), "=r"(r[7]),
          "=r"(r[8]), "=r"(r[9]), "=r"(r[10]), "=r"(r[11]),
          "=r"(r[12]), "=r"(r[13]), "=r"(r[14]), "=r"(r[15]),
          "=r"(r[16]), "=r"(r[17]), "=r"(r[18]), "=r"(r[19]),
          "=r"(r[20]), "=r"(r[21]), "=r"(r[22]), "=r"(r[23]),
          "=r"(r[24]), "=r"(r[25]), "=r"(r[26]), "=r"(r[27]),
          "=r"(r[28]), "=r"(r[29]), "=r"(r[30]), "=r"(r[31])
        : "r"(addr));
}
__device__ __forceinline__ void tc_wait_ld() {
    asm volatile("tcgen05.wait::ld.sync.aligned;" ::: "memory");
}
// SW128 K-major SMEM descriptor (version=1, LBO=1, SBO=64)
__device__ __forceinline__ uint64_t make_desc(uint32_t smem_addr) {
    const uint64_t base =
        (uint64_t(2) << 61) | (uint64_t(1) << 46) | (uint64_t(64) << 32) | (uint64_t(1) << 16);
    return base | ((uint64_t)(smem_addr >> 4) & 0x3FFF);
}
// idesc: kind::f16, dtype=F32(1<<4), atype=btype=F16(0), N=256 (32<<17), M=128 (8<<24)
#define IDESC 0x8400010u
#endif  // TC_PATH

// ---------------------------------------------------------------------------
// k1: dequant int4 -> g_W, tiled-swizzled [N/256][K/64][2][16KB]
// ---------------------------------------------------------------------------
__global__ void dequant_kernel(const int* __restrict__ packed,
                               const float* __restrict__ scale_p,
                               int total_bytes, int K) {
    int t = blockIdx.x * blockDim.x + threadIdx.x;
    if (t * 4 >= total_bytes) return;
    const float s = __ldg(scale_p);
    const int K2 = K >> 1;
    const int KC = K / KC_ELEMS;
    const int4 v = reinterpret_cast<const int4*>(packed)[t];

    int n  = (t * 4) / K2;
    int k0 = ((t * 4) % K2) * 2;     // multiple of 8

    __half out[8];
    const int b[4] = {v.x, v.y, v.z, v.w};
#pragma unroll
    for (int j = 0; j < 4; ++j) {
        int hi = b[j] >> 4;
        int lo = ((b[j] & 15) ^ 8) - 8;
        out[2 * j]     = __float2half_rn((float)hi * s);
        out[2 * j + 1] = __float2half_rn((float)lo * s);
    }

    int n2   = n >> 8;
    int half = (n >> 7) & 1;
    int r    = n & 127;
    int kc   = k0 >> 6;
    int c    = k0 & 63;
    size_t blk = ((size_t)n2 * KC + kc) * 2 + half;
    size_t off = blk * BLK_BYTES + swz128((uint32_t)(r * 128 + c * 2));
    *reinterpret_cast<uint4*>(reinterpret_cast<char*>(g_W) + off) =
        *reinterpret_cast<const uint4*>(out);
}

// ---------------------------------------------------------------------------
// k2: x fp32 -> g_X, tiled-swizzled [M/128][K/64][16KB]
// ---------------------------------------------------------------------------
__global__ void convert_x_kernel(const float* __restrict__ x, int total, int K) {
    int t = blockIdx.x * blockDim.x + threadIdx.x;
    if (t * 8 >= total) return;
    const int KC = K / KC_ELEMS;
    float4 a = reinterpret_cast<const float4*>(x)[t * 2];
    float4 c4 = reinterpret_cast<const float4*>(x)[t * 2 + 1];
    __half out[8];
    out[0] = __float2half_rn(a.x);  out[1] = __float2half_rn(a.y);
    out[2] = __float2half_rn(a.z);  out[3] = __float2half_rn(a.w);
    out[4] = __float2half_rn(c4.x); out[5] = __float2half_rn(c4.y);
    out[6] = __float2half_rn(c4.z); out[7] = __float2half_rn(c4.w);

    int m  = (t * 8) / K;
    int k0 = (t * 8) % K;
    int mb = m >> 7;
    int r  = m & 127;
    int kc = k0 >> 6;
    int c  = k0 & 63;
    size_t blk = (size_t)mb * KC + kc;
    size_t off = blk * BLK_BYTES + swz128((uint32_t)(r * 128 + c * 2));
    *reinterpret_cast<uint4*>(reinterpret_cast<char*>(g_X) + off) =
        *reinterpret_cast<const uint4*>(out);
}

// ---------------------------------------------------------------------------
// k3: GEMM. grid = (N/256, M/128), block = 256 threads, ~193KB dyn smem.
// ---------------------------------------------------------------------------
__global__ __launch_bounds__(256, 1)
void gemm_kernel(const float* __restrict__ bias,
                 float* __restrict__ Out,
                 int M, int N, int K) {
    extern __shared__ char smem[];
    const uint32_t sbase = smem_u32(smem);
    const int tid  = threadIdx.x;
    const int wid  = tid >> 5;
    const int lane = tid & 31;

    const int KC  = K / KC_ELEMS;                // 64 chunks
    const int nb2 = blockIdx.x;                  // N/256 tile
    const int mb  = blockIdx.y;                  // M/128 tile

    const char* Asrc = reinterpret_cast<const char*>(g_X) +
                       (size_t)mb * KC * BLK_BYTES;
    const char* Bsrc = reinterpret_cast<const char*>(g_W) +
                       (size_t)nb2 * KC * 2 * BLK_BYTES;

#if TC_PATH
    // ======================= tcgen05 path (sm_103a) =======================
    const uint32_t full0  = sbase;               // full[s]  : +0  + s*8
    const uint32_t empty0 = sbase + 32;          // empty[s] : +32 + s*8
    const uint32_t doneb  = sbase + 64;
    const uint32_t tslot  = sbase + 128;

    if (tid == 0) {
#pragma unroll
        for (int s = 0; s < STAGES; ++s) {
            mbar_init(full0 + s * 8, 1);
            mbar_init(empty0 + s * 8, 1);
        }
        mbar_init(doneb, 1);
    }
    __syncthreads();

    if (wid == 0) {
        tmem_alloc(tslot, 256);
        tmem_relinquish();
    }
    __syncthreads();
    uint32_t tmem_base;
    asm volatile("ld.shared.b32 %0, [%1];" : "=r"(tmem_base) : "r"(tslot));

    // ---- producer: thread 0 ----
    if (tid == 0) {
        int s = 0, phase = 1;                    // empty starts "available"
        for (int i = 0; i < KC; ++i) {
            mbar_wait(empty0 + s * 8, phase);
            const uint32_t fb = full0 + s * 8;
            mbar_expect_tx(fb, STAGE_BYTES);
            const uint32_t stg = sbase + SMEM_STAGE0 + s * STAGE_BYTES;
            bulk_g2s(stg,             Asrc + (size_t)i * BLK_BYTES,     BLK_BYTES,     fb);
            bulk_g2s(stg + BLK_BYTES, Bsrc + (size_t)i * 2 * BLK_BYTES, 2 * BLK_BYTES, fb);
            if (++s == STAGES) { s = 0; phase ^= 1; }
        }
    }

    // ---- MMA issuer: thread 32 ----
    if (tid == 32) {
        int s = 0, phase = 0;
        for (int i = 0; i < KC; ++i) {
            mbar_wait(full0 + s * 8, phase);
            const uint32_t stg = sbase + SMEM_STAGE0 + s * STAGE_BYTES;
            uint64_t ad = make_desc(stg);
            uint64_t bd = make_desc(stg + BLK_BYTES);
#pragma unroll
            for (int ks = 0; ks < 4; ++ks) {
                mma_f16_ss(tmem_base, ad + ks * 2, bd + ks * 2, IDESC,
                           (i > 0 || ks > 0) ? 1u : 0u);
            }
            tc_commit(empty0 + s * 8);           // stage reusable when MMAs drain
            if (++s == STAGES) { s = 0; phase ^= 1; }
        }
        tc_commit(doneb);
    }

    // ---- epilogue: 8 warps; warp w = subpartition (w&3), col half (w>>2) ----
    mbar_wait(doneb, 0);
    tc_fence_after();

    const int subp    = wid & 3;
    const int colhalf = wid >> 2;                // 0: cols 0..127, 1: 128..255
    const int row = mb * 128 + subp * 32 + lane;
    float* orow = Out + (size_t)row * N + nb2 * 256 + colhalf * 128;
    const float* brow = bias + nb2 * 256 + colhalf * 128;

#pragma unroll
    for (int cb = 0; cb < 4; ++cb) {
        uint32_t r32[32];
        ldtm_x32(r32, tmem_base + colhalf * 128 + cb * 32);
        tc_wait_ld();
        float o[32];
#pragma unroll
        for (int c = 0; c < 32; ++c) {
            __half h  = __float2half_rn(__uint_as_float(r32[c]));
            __half hb = __float2half_rn(__ldg(brow + cb * 32 + c));
            o[c] = __half2float(__hadd(h, hb));
        }
#pragma unroll
        for (int q = 0; q < 8; ++q) {
            reinterpret_cast<float4*>(orow + cb * 32)[q] =
                make_float4(o[4 * q], o[4 * q + 1], o[4 * q + 2], o[4 * q + 3]);
        }
    }

    __syncthreads();
    if (wid == 0) tmem_dealloc(tmem_base, 256);

#else
    // =================== mma.sync fallback (non-103a pass) ===================
    // 2-stage cp.async double buffer over the same swizzled layout.
    const int wm = wid >> 2;                     // 0..1 -> 64-row slab
    const int wn = wid & 3;                      // 0..3 -> 64-col slab

    float acc[4][8][4];
#pragma unroll
    for (int mf = 0; mf < 4; ++mf)
#pragma unroll
        for (int nf = 0; nf < 8; ++nf)
#pragma unroll
            for (int e = 0; e < 4; ++e) acc[mf][nf][e] = 0.0f;

    auto load_tile = [&](int buf, int i) {
        char* sa = smem + SMEM_STAGE0 + buf * STAGE_BYTES;
        const char* ga = Asrc + (size_t)i * BLK_BYTES;
        const char* gb = Bsrc + (size_t)i * 2 * BLK_BYTES;
#pragma unroll
        for (int u = 0; u < 4; ++u) {            // A: 1024 x 16B
            int off = (tid + u * 256) * 16;
            cp_async16(sa + off, ga + off);
        }
#pragma unroll
        for (int u = 0; u < 8; ++u) {            // B: 2048 x 16B
            int off = (tid + u * 256) * 16;
            cp_async16(sa + BLK_BYTES + off, gb + off);
        }
    };

    load_tile(0, 0);
    cp_commit();
    cp_wait<0>();
    __syncthreads();

    for (int kt = 0; kt < KC; ++kt) {
        const int buf = kt & 1;
        if (kt + 1 < KC) { load_tile(buf ^ 1, kt + 1); cp_commit(); }

        const char* sA = smem + SMEM_STAGE0 + buf * STAGE_BYTES;
        const char* sB = sA + BLK_BYTES;

#pragma unroll
        for (int ks = 0; ks < 4; ++ks) {
            const int colb = (ks * 16 + (lane >> 4) * 8) * 2;
            uint32_t a[4][4];
#pragma unroll
            for (int mf = 0; mf < 4; ++mf) {
                int r = wm * 64 + mf * 16 + (lane & 15);
                ldmatrix_x4(a[mf][0], a[mf][1], a[mf][2], a[mf][3],
                            sA + swz128(r * 128 + colb));
            }
            uint32_t b[8][2];
#pragma unroll
            for (int np = 0; np < 4; ++np) {
                int rb = wn * 64 + np * 16 + (lane & 15);
                const char* base = sB + (rb >> 7) * BLK_BYTES;
                uint32_t r0, r1, r2, r3;
                ldmatrix_x4(r0, r1, r2, r3,
                            base + swz128((rb & 127) * 128 + colb));
                b[np * 2][0]     = r0;
                b[np * 2][1]     = r2;
                b[np * 2 + 1][0] = r1;
                b[np * 2 + 1][1] = r3;
            }
#pragma unroll
            for (int mf = 0; mf < 4; ++mf)
#pragma unroll
                for (int nf = 0; nf < 8; ++nf)
                    mma16816(acc[mf][nf],
                             a[mf][0], a[mf][1], a[mf][2], a[mf][3],
                             b[nf][0], b[nf][1]);
        }

        if (kt + 1 < KC) cp_wait<0>();
        __syncthreads();
    }

    const int bm = mb * 128, bn = nb2 * 256;
#pragma unroll
    for (int mf = 0; mf < 4; ++mf) {
        const int row0 = bm + wm * 64 + mf * 16 + (lane >> 2);
#pragma unroll
        for (int nf = 0; nf < 8; ++nf) {
            const int col = bn + wn * 64 + nf * 8 + (lane & 3) * 2;
            const float2 bf = *reinterpret_cast<const float2*>(bias + col);
            const __half2 bb = __floats2half2_rn(bf.x, bf.y);
            __half2 v0 = __hadd2(__floats2half2_rn(acc[mf][nf][0], acc[mf][nf][1]), bb);
            __half2 v1 = __hadd2(__floats2half2_rn(acc[mf][nf][2], acc[mf][nf][3]), bb);
            float2 o0 = __half22float2(v0);
            float2 o1 = __half22float2(v1);
            *reinterpret_cast<float2*>(Out + (size_t)row0 * N + col)       = o0;
            *reinterpret_cast<float2*>(Out + (size_t)(row0 + 8) * N + col) = o1;
        }
    }
#endif
}

// ---------------------------------------------------------------------------
extern "C" void kernel_launch(void* const* d_in, const int* in_sizes, int n_in,
                              void* d_out, int out_size) {
    const float* x     = (const float*)d_in[0];
    const int*   wq    = (const int*)d_in[1];
    const float* scale = (const float*)d_in[2];
    const float* bias  = (const float*)d_in[3];
    float*       out   = (float*)d_out;

    const int O = in_sizes[3];                    // 4096
    const int K = (in_sizes[1] / O) * 2;          // 4096
    const int M = in_sizes[0] / K;                // 8192
    const int N = O;

    const int nbytes = in_sizes[1];
    dequant_kernel<<<(nbytes / 4 + 255) / 256, 256>>>(wq, scale, nbytes, K);

    const int nx = in_sizes[0];
    convert_x_kernel<<<(nx / 8 + 255) / 256, 256>>>(x, nx, K);

    cudaFuncSetAttribute(gemm_kernel,
                         cudaFuncAttributeMaxDynamicSharedMemorySize,
                         SMEM_TOTAL_GEMM);
    dim3 grid(N / 256, M / 128);
    gemm_kernel<<<grid, 256, SMEM_TOTAL_GEMM>>>(bias, out, M, N, K);
}